// round 7
// baseline (speedup 1.0000x reference)
#include <cuda_runtime.h>
#include <cuda_bf16.h>
#include <cuda_fp16.h>
#include <cstdint>

#define IN_F   256
#define OUT_F  128
#define NNODES 100000

// support = X @ W stored as fp16 (halves aggregate gather traffic)
__device__ __half2 g_support_h[(size_t)NNODES * (OUT_F / 2)];
// Preconverted weight (fp16)
__device__ __half  g_wh[IN_F * OUT_F];

// ===========================================================================
// Helpers
// ===========================================================================
__device__ __forceinline__ uint32_t smem_u32(const void* p) {
    uint32_t a;
    asm("{ .reg .u64 t; cvta.to.shared.u64 t, %1; cvt.u32.u64 %0, t; }"
        : "=r"(a) : "l"(p));
    return a;
}
__device__ __forceinline__ void ldsm_x4(uint32_t* r, uint32_t addr) {
    asm volatile("ldmatrix.sync.aligned.m8n8.x4.shared.b16 {%0,%1,%2,%3}, [%4];"
                 : "=r"(r[0]), "=r"(r[1]), "=r"(r[2]), "=r"(r[3]) : "r"(addr));
}
__device__ __forceinline__ void ldsm_x4_t(uint32_t* r, uint32_t addr) {
    asm volatile("ldmatrix.sync.aligned.m8n8.x4.trans.shared.b16 {%0,%1,%2,%3}, [%4];"
                 : "=r"(r[0]), "=r"(r[1]), "=r"(r[2]), "=r"(r[3]) : "r"(addr));
}
__device__ __forceinline__ void mma_fp16(float* c, const uint32_t* a, const uint32_t* b) {
    asm volatile(
        "mma.sync.aligned.m16n8k16.row.col.f32.f16.f16.f32 "
        "{%0,%1,%2,%3}, {%4,%5,%6,%7}, {%8,%9}, {%0,%1,%2,%3};"
        : "+f"(c[0]), "+f"(c[1]), "+f"(c[2]), "+f"(c[3])
        : "r"(a[0]), "r"(a[1]), "r"(a[2]), "r"(a[3]), "r"(b[0]), "r"(b[1]));
}
__device__ __forceinline__ uint32_t packh2(float x, float y) {
    __half2 h = __floats2half2_rn(x, y);
    return *reinterpret_cast<uint32_t*>(&h);
}

// ===========================================================================
// Kernel 0: W fp32 -> fp16 convert (tiny)
// ===========================================================================
__global__ void convert_w_kernel(const float* __restrict__ W)
{
    int i = blockIdx.x * 256 + threadIdx.x;
    if (i < IN_F * OUT_F)
        g_wh[i] = __float2half_rn(W[i]);
}

// ===========================================================================
// Kernel 1: GEMM  support[M,128] = X[M,256] @ W[256,128], fp16 MMA.
// Block 128x128, 8 warps (2x4), warp tile 64x32, BK=32 fp32.
// Whole W resident in SMEM; A tiles double-buffered; 2 CTAs/SM.
// ===========================================================================
#define BKC 32
#define A_STRIDE 40
#define B_STRIDE 136
#define A_BUF_BYTES (128 * A_STRIDE * 2)
#define SM_A   0
#define SM_B   (2 * A_BUF_BYTES)
#define SM_TOTAL (SM_B + IN_F * B_STRIDE * 2)      // 90112

__global__ void __launch_bounds__(256, 2)
gemm_mma_kernel(const float* __restrict__ X, int M)
{
    extern __shared__ __align__(16) char smem[];
    const uint32_t sb = smem_u32(smem);

    const int tid    = threadIdx.x;
    const int lane   = tid & 31;
    const int wid    = tid >> 5;
    const int warp_m = (wid & 1) * 64;
    const int warp_n = (wid >> 1) * 32;
    const int row0   = blockIdx.x << 7;

    {
        const uint4* wp = reinterpret_cast<const uint4*>(g_wh);
        #pragma unroll
        for (int i = 0; i < 16; i++) {
            int e = tid + i * 256;
            int k = e >> 4, u = e & 15;
            uint4 h = wp[(size_t)k * 16 + u];
            uint32_t off = (uint32_t)(k * (B_STRIDE * 2) + u * 16);
            asm volatile("st.shared.v4.b32 [%0], {%1,%2,%3,%4};"
                         :: "r"(sb + SM_B + off), "r"(h.x), "r"(h.y), "r"(h.z), "r"(h.w) : "memory");
        }
    }

    float acc[4][4][4];
    #pragma unroll
    for (int i = 0; i < 4; i++)
        #pragma unroll
        for (int j = 0; j < 4; j++)
            #pragma unroll
            for (int q = 0; q < 4; q++) acc[i][j][q] = 0.f;

    const int a_r  = tid >> 3;
    const int a_kq = tid & 7;

    float4 xa[4];
    #pragma unroll
    for (int i = 0; i < 4; i++) {
        int gr = row0 + a_r + i * 32;
        xa[i] = (gr < M) ? *reinterpret_cast<const float4*>(X + (size_t)gr * IN_F + a_kq * 4)
                         : make_float4(0.f, 0.f, 0.f, 0.f);
    }
    #pragma unroll
    for (int i = 0; i < 4; i++) {
        int r = a_r + i * 32;
        uint32_t h0 = packh2(xa[i].x, xa[i].y), h1 = packh2(xa[i].z, xa[i].w);
        uint32_t off = (uint32_t)(r * (A_STRIDE * 2) + a_kq * 8);
        asm volatile("st.shared.v2.b32 [%0], {%1,%2};" :: "r"(sb + SM_A + off), "r"(h0), "r"(h1) : "memory");
    }
    __syncthreads();

    for (int c = 0; c < IN_F / BKC; c++) {
        const uint32_t abuf = sb + SM_A + (uint32_t)(c & 1) * A_BUF_BYTES;
        const bool more = (c + 1 < IN_F / BKC);

        if (more) {
            int k0n = (c + 1) * BKC;
            #pragma unroll
            for (int i = 0; i < 4; i++) {
                int gr = row0 + a_r + i * 32;
                xa[i] = (gr < M) ? *reinterpret_cast<const float4*>(X + (size_t)gr * IN_F + k0n + a_kq * 4)
                                 : make_float4(0.f, 0.f, 0.f, 0.f);
            }
        }

        #pragma unroll
        for (int ks = 0; ks < 2; ks++) {
            uint32_t ah[4][4], bh[2][4];
            const uint32_t a_col = (uint32_t)((ks * 16 + (lane >> 4) * 8) * 2);
            #pragma unroll
            for (int mi = 0; mi < 4; mi++) {
                uint32_t ar = (uint32_t)((warp_m + mi * 16 + (lane & 15)) * (A_STRIDE * 2)) + a_col;
                ldsm_x4(ah[mi], abuf + ar);
            }
            const uint32_t b_row =
                (uint32_t)((c * 32 + ks * 16 + (lane & 7) + ((lane >> 3) & 1) * 8) * (B_STRIDE * 2));
            #pragma unroll
            for (int nj = 0; nj < 2; nj++) {
                uint32_t br = b_row + (uint32_t)((warp_n + nj * 16 + (lane >> 4) * 8) * 2);
                ldsm_x4_t(bh[nj], sb + SM_B + br);
            }
            #pragma unroll
            for (int mi = 0; mi < 4; mi++) {
                #pragma unroll
                for (int nj = 0; nj < 4; nj++) {
                    uint32_t bf[2] = { bh[nj >> 1][(nj & 1) * 2], bh[nj >> 1][(nj & 1) * 2 + 1] };
                    mma_fp16(acc[mi][nj], ah[mi], bf);
                }
            }
        }

        if (more) {
            const uint32_t nbuf = sb + SM_A + (uint32_t)((c + 1) & 1) * A_BUF_BYTES;
            #pragma unroll
            for (int i = 0; i < 4; i++) {
                int r = a_r + i * 32;
                uint32_t h0 = packh2(xa[i].x, xa[i].y), h1 = packh2(xa[i].z, xa[i].w);
                uint32_t off = (uint32_t)(r * (A_STRIDE * 2) + a_kq * 8);
                asm volatile("st.shared.v2.b32 [%0], {%1,%2};" :: "r"(nbuf + off), "r"(h0), "r"(h1) : "memory");
            }
        }
        __syncthreads();
    }

    #pragma unroll
    for (int mi = 0; mi < 4; mi++) {
        int r_lo = row0 + warp_m + mi * 16 + (lane >> 2);
        int r_hi = r_lo + 8;
        #pragma unroll
        for (int nj = 0; nj < 4; nj++) {
            int col = warp_n + nj * 8 + (lane & 3) * 2;
            if (r_lo < M)
                g_support_h[(size_t)r_lo * (OUT_F / 2) + (col >> 1)] =
                    __floats2half2_rn(acc[mi][nj][0], acc[mi][nj][1]);
            if (r_hi < M)
                g_support_h[(size_t)r_hi * (OUT_F / 2) + (col >> 1)] =
                    __floats2half2_rn(acc[mi][nj][2], acc[mi][nj][3]);
        }
    }
}

// ===========================================================================
// Kernel 2: aggregation + bias + tanh. No precomputed CSR:
// each 256-thread block (8 warps = 8 nodes) binary-searches its 9 segment
// bounds in the sorted dst array (9 threads, 21 cached steps each).
// Inner loop: 8-edge unroll -> 8 independent gathers in flight (MLP=8).
// ===========================================================================
#define FMA4(vv, rr)                                                         \
    do {                                                                     \
        float2 _f0 = __half22float2(*reinterpret_cast<__half2*>(&(rr).x));   \
        float2 _f1 = __half22float2(*reinterpret_cast<__half2*>(&(rr).y));   \
        a0 += (vv) * _f0.x; a1 += (vv) * _f0.y;                              \
        a2 += (vv) * _f1.x; a3 += (vv) * _f1.y;                              \
    } while (0)

__global__ __launch_bounds__(256)
void aggregate_kernel(const int*   __restrict__ src,
                      const float* __restrict__ val,
                      const int*   __restrict__ dst,
                      const float* __restrict__ bias,
                      float*       __restrict__ out,
                      int N, int E)
{
    __shared__ int bounds[9];
    const int node0 = blockIdx.x * 8;
    const int tid   = threadIdx.x;

    if (tid < 9) {
        int target = node0 + tid;          // lower_bound(target) in dst
        int lo = 0, hi = E;
        while (lo < hi) {
            int mid = (lo + hi) >> 1;
            if (__ldg(dst + mid) < target) lo = mid + 1; else hi = mid;
        }
        bounds[tid] = lo;
    }
    __syncthreads();

    const int wid = tid >> 5;
    const int n   = node0 + wid;
    if (n >= N) return;
    const int lane = tid & 31;

    const uint2* __restrict__ sup = reinterpret_cast<const uint2*>(g_support_h);

    int i = bounds[wid];
    const int e = bounds[wid + 1];

    float a0 = 0.f, a1 = 0.f, a2 = 0.f, a3 = 0.f;

    // head: align to 4 for vector src/val loads
    for (; i < e && (i & 3); i++) {
        float v = val[i];
        uint2 r = __ldg(sup + ((uint32_t)src[i] << 5) + lane);
        FMA4(v, r);
    }
    // main: 8-edge unroll, 8 gathers in flight
    for (; i + 8 <= e; i += 8) {
        int4   sA = *reinterpret_cast<const int4*>(src + i);
        int4   sB = *reinterpret_cast<const int4*>(src + i + 4);
        float4 vA = *reinterpret_cast<const float4*>(val + i);
        float4 vB = *reinterpret_cast<const float4*>(val + i + 4);
        uint2 r0 = __ldg(sup + ((uint32_t)sA.x << 5) + lane);
        uint2 r1 = __ldg(sup + ((uint32_t)sA.y << 5) + lane);
        uint2 r2 = __ldg(sup + ((uint32_t)sA.z << 5) + lane);
        uint2 r3 = __ldg(sup + ((uint32_t)sA.w << 5) + lane);
        uint2 r4 = __ldg(sup + ((uint32_t)sB.x << 5) + lane);
        uint2 r5 = __ldg(sup + ((uint32_t)sB.y << 5) + lane);
        uint2 r6 = __ldg(sup + ((uint32_t)sB.z << 5) + lane);
        uint2 r7 = __ldg(sup + ((uint32_t)sB.w << 5) + lane);
        FMA4(vA.x, r0); FMA4(vA.y, r1); FMA4(vA.z, r2); FMA4(vA.w, r3);
        FMA4(vB.x, r4); FMA4(vB.y, r5); FMA4(vB.z, r6); FMA4(vB.w, r7);
    }
    // tail: 4-wide then scalar
    for (; i + 4 <= e; i += 4) {
        int4   sA = *reinterpret_cast<const int4*>(src + i);
        float4 vA = *reinterpret_cast<const float4*>(val + i);
        uint2 r0 = __ldg(sup + ((uint32_t)sA.x << 5) + lane);
        uint2 r1 = __ldg(sup + ((uint32_t)sA.y << 5) + lane);
        uint2 r2 = __ldg(sup + ((uint32_t)sA.z << 5) + lane);
        uint2 r3 = __ldg(sup + ((uint32_t)sA.w << 5) + lane);
        FMA4(vA.x, r0); FMA4(vA.y, r1); FMA4(vA.z, r2); FMA4(vA.w, r3);
    }
    for (; i < e; i++) {
        float v = val[i];
        uint2 r = __ldg(sup + ((uint32_t)src[i] << 5) + lane);
        FMA4(v, r);
    }

    float4 b = *reinterpret_cast<const float4*>(bias + lane * 4);
    *reinterpret_cast<float4*>(out + (size_t)n * OUT_F + lane * 4) =
        make_float4(tanhf(a0 + b.x), tanhf(a1 + b.y),
                    tanhf(a2 + b.z), tanhf(a3 + b.w));
}

// ===========================================================================
// Launch
// ===========================================================================
extern "C" void kernel_launch(void* const* d_in, const int* in_sizes, int n_in,
                              void* d_out, int out_size)
{
    const float* x        = (const float*)d_in[0];
    const float* weight   = (const float*)d_in[1];
    const float* bias     = (const float*)d_in[2];
    const int*   edge_src = (const int*)  d_in[3];
    const int*   edge_dst = (const int*)  d_in[4];
    const float* edge_val = (const float*)d_in[5];
    float*       out      = (float*)d_out;

    const int M = in_sizes[0] / IN_F;   // 100000
    const int E = in_sizes[3];          // 1600000

    static bool attr_done = false;
    if (!attr_done) {
        cudaFuncSetAttribute(gemm_mma_kernel,
                             cudaFuncAttributeMaxDynamicSharedMemorySize, SM_TOTAL);
        attr_done = true;
    }

    // 0) W fp16 convert (tiny)
    convert_w_kernel<<<(IN_F * OUT_F + 255) / 256, 256>>>(weight);
    // 1) support = X @ W on tensor cores (fp16)
    gemm_mma_kernel<<<(M + 127) / 128, 256, SM_TOTAL>>>(x, M);
    // 2) gather + segment-sum + bias + tanh (warp/node, self-searched bounds)
    aggregate_kernel<<<(M + 7) / 8, 256>>>(edge_src, edge_val, edge_dst,
                                           bias, out, M, E);
}

// round 8
// speedup vs baseline: 1.2881x; 1.2881x over previous
#include <cuda_runtime.h>
#include <cuda_bf16.h>
#include <cuda_fp16.h>
#include <cstdint>

#define IN_F   256
#define OUT_F  128
#define NNODES 100000

// support = X @ W stored as fp16 (halves aggregate gather traffic)
__device__ __half2 g_support_h[(size_t)NNODES * (OUT_F / 2)];
__device__ int     g_row_start[NNODES + 1];

// ===========================================================================
// Helpers
// ===========================================================================
__device__ __forceinline__ uint32_t smem_u32(const void* p) {
    uint32_t a;
    asm("{ .reg .u64 t; cvta.to.shared.u64 t, %1; cvt.u32.u64 %0, t; }"
        : "=r"(a) : "l"(p));
    return a;
}
__device__ __forceinline__ void ldsm_x4(uint32_t* r, uint32_t addr) {
    asm volatile("ldmatrix.sync.aligned.m8n8.x4.shared.b16 {%0,%1,%2,%3}, [%4];"
                 : "=r"(r[0]), "=r"(r[1]), "=r"(r[2]), "=r"(r[3]) : "r"(addr));
}
__device__ __forceinline__ void ldsm_x4_t(uint32_t* r, uint32_t addr) {
    asm volatile("ldmatrix.sync.aligned.m8n8.x4.trans.shared.b16 {%0,%1,%2,%3}, [%4];"
                 : "=r"(r[0]), "=r"(r[1]), "=r"(r[2]), "=r"(r[3]) : "r"(addr));
}
__device__ __forceinline__ void mma_fp16(float* c, const uint32_t* a, const uint32_t* b) {
    asm volatile(
        "mma.sync.aligned.m16n8k16.row.col.f32.f16.f16.f32 "
        "{%0,%1,%2,%3}, {%4,%5,%6,%7}, {%8,%9}, {%0,%1,%2,%3};"
        : "+f"(c[0]), "+f"(c[1]), "+f"(c[2]), "+f"(c[3])
        : "r"(a[0]), "r"(a[1]), "r"(a[2]), "r"(a[3]), "r"(b[0]), "r"(b[1]));
}
__device__ __forceinline__ uint32_t packh2(float x, float y) {
    __half2 h = __floats2half2_rn(x, y);
    return *reinterpret_cast<uint32_t*>(&h);
}

// ===========================================================================
// Kernel 1: GEMM  support[M,128] = X[M,256] @ W[256,128], fp16 MMA.
// Block 128x128, 8 warps (2x4), warp tile 64x32, BK=32 fp32; 2 CTAs/SM.
// W converted fp32->fp16 in-prologue (L2-resident after CTA 0).
// CSR boundary scan folded into the kernel tail (hidden in CTA stagger).
// ===========================================================================
#define BKC 32
#define A_STRIDE 40
#define B_STRIDE 136
#define A_BUF_BYTES (128 * A_STRIDE * 2)
#define SM_A   0
#define SM_B   (2 * A_BUF_BYTES)
#define SM_TOTAL (SM_B + IN_F * B_STRIDE * 2)      // 90112

__global__ void __launch_bounds__(256, 2)
gemm_mma_kernel(const float* __restrict__ X, const float* __restrict__ W,
                const int* __restrict__ dst, int M, int E)
{
    extern __shared__ __align__(16) char smem[];
    const uint32_t sb = smem_u32(smem);

    const int tid    = threadIdx.x;
    const int lane   = tid & 31;
    const int wid    = tid >> 5;
    const int warp_m = (wid & 1) * 64;
    const int warp_n = (wid >> 1) * 32;
    const int row0   = blockIdx.x << 7;

    // ---- prologue: W fp32 -> fp16 into SMEM (256 k-rows resident) ----
    {
        #pragma unroll
        for (int i = 0; i < 16; i++) {
            int e = tid + i * 256;          // 4096 units of 8 fp16 (16B smem)
            int k = e >> 4, u = e & 15;
            const float4* wsrc = reinterpret_cast<const float4*>(W + (size_t)e * 8);
            float4 f0 = wsrc[0];
            float4 f1 = wsrc[1];
            uint32_t p0 = packh2(f0.x, f0.y), p1 = packh2(f0.z, f0.w);
            uint32_t p2 = packh2(f1.x, f1.y), p3 = packh2(f1.z, f1.w);
            uint32_t off = (uint32_t)(k * (B_STRIDE * 2) + u * 16);
            asm volatile("st.shared.v4.b32 [%0], {%1,%2,%3,%4};"
                         :: "r"(sb + SM_B + off), "r"(p0), "r"(p1), "r"(p2), "r"(p3) : "memory");
        }
    }

    float acc[4][4][4];
    #pragma unroll
    for (int i = 0; i < 4; i++)
        #pragma unroll
        for (int j = 0; j < 4; j++)
            #pragma unroll
            for (int q = 0; q < 4; q++) acc[i][j][q] = 0.f;

    const int a_r  = tid >> 3;
    const int a_kq = tid & 7;

    float4 xa[4];
    #pragma unroll
    for (int i = 0; i < 4; i++) {
        int gr = row0 + a_r + i * 32;
        xa[i] = (gr < M) ? *reinterpret_cast<const float4*>(X + (size_t)gr * IN_F + a_kq * 4)
                         : make_float4(0.f, 0.f, 0.f, 0.f);
    }
    #pragma unroll
    for (int i = 0; i < 4; i++) {
        int r = a_r + i * 32;
        uint32_t h0 = packh2(xa[i].x, xa[i].y), h1 = packh2(xa[i].z, xa[i].w);
        uint32_t off = (uint32_t)(r * (A_STRIDE * 2) + a_kq * 8);
        asm volatile("st.shared.v2.b32 [%0], {%1,%2};" :: "r"(sb + SM_A + off), "r"(h0), "r"(h1) : "memory");
    }
    __syncthreads();

    for (int c = 0; c < IN_F / BKC; c++) {
        const uint32_t abuf = sb + SM_A + (uint32_t)(c & 1) * A_BUF_BYTES;
        const bool more = (c + 1 < IN_F / BKC);

        if (more) {
            int k0n = (c + 1) * BKC;
            #pragma unroll
            for (int i = 0; i < 4; i++) {
                int gr = row0 + a_r + i * 32;
                xa[i] = (gr < M) ? *reinterpret_cast<const float4*>(X + (size_t)gr * IN_F + k0n + a_kq * 4)
                                 : make_float4(0.f, 0.f, 0.f, 0.f);
            }
        }

        #pragma unroll
        for (int ks = 0; ks < 2; ks++) {
            uint32_t ah[4][4], bh[2][4];
            const uint32_t a_col = (uint32_t)((ks * 16 + (lane >> 4) * 8) * 2);
            #pragma unroll
            for (int mi = 0; mi < 4; mi++) {
                uint32_t ar = (uint32_t)((warp_m + mi * 16 + (lane & 15)) * (A_STRIDE * 2)) + a_col;
                ldsm_x4(ah[mi], abuf + ar);
            }
            const uint32_t b_row =
                (uint32_t)((c * 32 + ks * 16 + (lane & 7) + ((lane >> 3) & 1) * 8) * (B_STRIDE * 2));
            #pragma unroll
            for (int nj = 0; nj < 2; nj++) {
                uint32_t br = b_row + (uint32_t)((warp_n + nj * 16 + (lane >> 4) * 8) * 2);
                ldsm_x4_t(bh[nj], sb + SM_B + br);
            }
            #pragma unroll
            for (int mi = 0; mi < 4; mi++) {
                #pragma unroll
                for (int nj = 0; nj < 4; nj++) {
                    uint32_t bf[2] = { bh[nj >> 1][(nj & 1) * 2], bh[nj >> 1][(nj & 1) * 2 + 1] };
                    mma_fp16(acc[mi][nj], ah[mi], bf);
                }
            }
        }

        if (more) {
            const uint32_t nbuf = sb + SM_A + (uint32_t)((c + 1) & 1) * A_BUF_BYTES;
            #pragma unroll
            for (int i = 0; i < 4; i++) {
                int r = a_r + i * 32;
                uint32_t h0 = packh2(xa[i].x, xa[i].y), h1 = packh2(xa[i].z, xa[i].w);
                uint32_t off = (uint32_t)(r * (A_STRIDE * 2) + a_kq * 8);
                asm volatile("st.shared.v2.b32 [%0], {%1,%2};" :: "r"(nbuf + off), "r"(h0), "r"(h1) : "memory");
            }
        }
        __syncthreads();
    }

    // ---- epilogue: accumulators -> g_support_h (fp16) ----
    #pragma unroll
    for (int mi = 0; mi < 4; mi++) {
        int r_lo = row0 + warp_m + mi * 16 + (lane >> 2);
        int r_hi = r_lo + 8;
        #pragma unroll
        for (int nj = 0; nj < 4; nj++) {
            int col = warp_n + nj * 8 + (lane & 3) * 2;
            if (r_lo < M)
                g_support_h[(size_t)r_lo * (OUT_F / 2) + (col >> 1)] =
                    __floats2half2_rn(acc[mi][nj][0], acc[mi][nj][1]);
            if (r_hi < M)
                g_support_h[(size_t)r_hi * (OUT_F / 2) + (col >> 1)] =
                    __floats2half2_rn(acc[mi][nj][2], acc[mi][nj][3]);
        }
    }

    // ---- folded CSR boundary scan (grid-stride over edge boundaries) ----
    {
        const int nthreads = gridDim.x << 8;
        for (int e = blockIdx.x * 256 + tid; e <= E; e += nthreads) {
            if (e == 0) {
                int d1 = __ldg(dst);
                for (int n = 0; n <= d1; n++) g_row_start[n] = 0;
            } else if (e == E) {
                int d0 = __ldg(dst + E - 1);
                for (int n = d0 + 1; n <= M; n++) g_row_start[n] = E;
            } else {
                int d0 = __ldg(dst + e - 1);
                int d1 = __ldg(dst + e);
                for (int n = d0 + 1; n <= d1; n++) g_row_start[n] = e;
            }
        }
    }
}

// ===========================================================================
// Kernel 2: aggregation + bias + tanh.
// One warp per node (4 nodes / 128-thread block), precomputed bounds,
// 8-edge unroll -> 8 independent gathers in flight.
// ===========================================================================
#define FMA4(vv, rr)                                                         \
    do {                                                                     \
        float2 _f0 = __half22float2(*reinterpret_cast<__half2*>(&(rr).x));   \
        float2 _f1 = __half22float2(*reinterpret_cast<__half2*>(&(rr).y));   \
        a0 += (vv) * _f0.x; a1 += (vv) * _f0.y;                              \
        a2 += (vv) * _f1.x; a3 += (vv) * _f1.y;                              \
    } while (0)

__global__ __launch_bounds__(128)
void aggregate_kernel(const int*   __restrict__ src,
                      const float* __restrict__ val,
                      const float* __restrict__ bias,
                      float*       __restrict__ out,
                      int N)
{
    const int n = blockIdx.x * 4 + (threadIdx.x >> 5);
    if (n >= N) return;
    const int lane = threadIdx.x & 31;

    const uint2* __restrict__ sup = reinterpret_cast<const uint2*>(g_support_h);

    int i       = g_row_start[n];
    const int e = g_row_start[n + 1];

    float a0 = 0.f, a1 = 0.f, a2 = 0.f, a3 = 0.f;

    for (; i < e && (i & 3); i++) {
        float v = val[i];
        uint2 r = __ldg(sup + ((uint32_t)src[i] << 5) + lane);
        FMA4(v, r);
    }
    for (; i + 8 <= e; i += 8) {
        int4   sA = *reinterpret_cast<const int4*>(src + i);
        int4   sB = *reinterpret_cast<const int4*>(src + i + 4);
        float4 vA = *reinterpret_cast<const float4*>(val + i);
        float4 vB = *reinterpret_cast<const float4*>(val + i + 4);
        uint2 r0 = __ldg(sup + ((uint32_t)sA.x << 5) + lane);
        uint2 r1 = __ldg(sup + ((uint32_t)sA.y << 5) + lane);
        uint2 r2 = __ldg(sup + ((uint32_t)sA.z << 5) + lane);
        uint2 r3 = __ldg(sup + ((uint32_t)sA.w << 5) + lane);
        uint2 r4 = __ldg(sup + ((uint32_t)sB.x << 5) + lane);
        uint2 r5 = __ldg(sup + ((uint32_t)sB.y << 5) + lane);
        uint2 r6 = __ldg(sup + ((uint32_t)sB.z << 5) + lane);
        uint2 r7 = __ldg(sup + ((uint32_t)sB.w << 5) + lane);
        FMA4(vA.x, r0); FMA4(vA.y, r1); FMA4(vA.z, r2); FMA4(vA.w, r3);
        FMA4(vB.x, r4); FMA4(vB.y, r5); FMA4(vB.z, r6); FMA4(vB.w, r7);
    }
    for (; i + 4 <= e; i += 4) {
        int4   sA = *reinterpret_cast<const int4*>(src + i);
        float4 vA = *reinterpret_cast<const float4*>(val + i);
        uint2 r0 = __ldg(sup + ((uint32_t)sA.x << 5) + lane);
        uint2 r1 = __ldg(sup + ((uint32_t)sA.y << 5) + lane);
        uint2 r2 = __ldg(sup + ((uint32_t)sA.z << 5) + lane);
        uint2 r3 = __ldg(sup + ((uint32_t)sA.w << 5) + lane);
        FMA4(vA.x, r0); FMA4(vA.y, r1); FMA4(vA.z, r2); FMA4(vA.w, r3);
    }
    for (; i < e; i++) {
        float v = val[i];
        uint2 r = __ldg(sup + ((uint32_t)src[i] << 5) + lane);
        FMA4(v, r);
    }

    float4 b = *reinterpret_cast<const float4*>(bias + lane * 4);
    *reinterpret_cast<float4*>(out + (size_t)n * OUT_F + lane * 4) =
        make_float4(tanhf(a0 + b.x), tanhf(a1 + b.y),
                    tanhf(a2 + b.z), tanhf(a3 + b.w));
}

// ===========================================================================
// Launch — 2 kernels total
// ===========================================================================
extern "C" void kernel_launch(void* const* d_in, const int* in_sizes, int n_in,
                              void* d_out, int out_size)
{
    const float* x        = (const float*)d_in[0];
    const float* weight   = (const float*)d_in[1];
    const float* bias     = (const float*)d_in[2];
    const int*   edge_src = (const int*)  d_in[3];
    const int*   edge_dst = (const int*)  d_in[4];
    const float* edge_val = (const float*)d_in[5];
    float*       out      = (float*)d_out;

    const int M = in_sizes[0] / IN_F;   // 100000
    const int E = in_sizes[3];          // 1600000

    static bool attr_done = false;
    if (!attr_done) {
        cudaFuncSetAttribute(gemm_mma_kernel,
                             cudaFuncAttributeMaxDynamicSharedMemorySize, SM_TOTAL);
        attr_done = true;
    }

    // 1) support = X @ W (tensor cores) + inline W convert + CSR scan in tail
    gemm_mma_kernel<<<(M + 127) / 128, 256, SM_TOTAL>>>(x, weight, edge_dst, M, E);
    // 2) gather + segment-sum + bias + tanh (one warp per node)
    aggregate_kernel<<<(M + 3) / 4, 128>>>(edge_src, edge_val, bias, out, M);
}

// round 9
// speedup vs baseline: 1.4645x; 1.1370x over previous
#include <cuda_runtime.h>
#include <cuda_bf16.h>
#include <cuda_fp16.h>
#include <cstdint>

#define IN_F   256
#define OUT_F  128
#define NNODES 100000

// support = X @ W stored as fp16 (halves aggregate gather traffic)
__device__ __half2 g_support_h[(size_t)NNODES * (OUT_F / 2)];
__device__ int     g_row_start[NNODES + 1];
// Preconverted weight (fp16)
__device__ __half  g_wh[IN_F * OUT_F];

// ===========================================================================
// Helpers
// ===========================================================================
__device__ __forceinline__ uint32_t smem_u32(const void* p) {
    uint32_t a;
    asm("{ .reg .u64 t; cvta.to.shared.u64 t, %1; cvt.u32.u64 %0, t; }"
        : "=r"(a) : "l"(p));
    return a;
}
__device__ __forceinline__ void ldsm_x4(uint32_t* r, uint32_t addr) {
    asm volatile("ldmatrix.sync.aligned.m8n8.x4.shared.b16 {%0,%1,%2,%3}, [%4];"
                 : "=r"(r[0]), "=r"(r[1]), "=r"(r[2]), "=r"(r[3]) : "r"(addr));
}
__device__ __forceinline__ void ldsm_x4_t(uint32_t* r, uint32_t addr) {
    asm volatile("ldmatrix.sync.aligned.m8n8.x4.trans.shared.b16 {%0,%1,%2,%3}, [%4];"
                 : "=r"(r[0]), "=r"(r[1]), "=r"(r[2]), "=r"(r[3]) : "r"(addr));
}
__device__ __forceinline__ void mma_fp16(float* c, const uint32_t* a, const uint32_t* b) {
    asm volatile(
        "mma.sync.aligned.m16n8k16.row.col.f32.f16.f16.f32 "
        "{%0,%1,%2,%3}, {%4,%5,%6,%7}, {%8,%9}, {%0,%1,%2,%3};"
        : "+f"(c[0]), "+f"(c[1]), "+f"(c[2]), "+f"(c[3])
        : "r"(a[0]), "r"(a[1]), "r"(a[2]), "r"(a[3]), "r"(b[0]), "r"(b[1]));
}
__device__ __forceinline__ uint32_t packh2(float x, float y) {
    __half2 h = __floats2half2_rn(x, y);
    return *reinterpret_cast<uint32_t*>(&h);
}

// ===========================================================================
// Kernel 0: prep — W fp32->fp16 convert + CSR row pointers.
// One thread per 8 edge boundaries: 2x int4 + 1 scalar load covers 8
// adjacent-pair comparisons (read dst once, not twice).
// ===========================================================================
__global__ void prep_kernel(const float* __restrict__ W,
                            const int* __restrict__ dst, int E, int N)
{
    const int gid = blockIdx.x * 256 + threadIdx.x;

    // ---- W convert: first 128 blocks' worth of threads ----
    if (gid < IN_F * OUT_F)
        g_wh[gid] = __float2half_rn(W[gid]);

    // ---- CSR boundaries: thread gid owns edges [8*gid, 8*gid+8) ----
    const int e0 = gid * 8;
    if (e0 > E) return;

    if (e0 + 8 <= E) {
        int4 dA = *reinterpret_cast<const int4*>(dst + e0);
        int4 dB = *reinterpret_cast<const int4*>(dst + e0 + 4);
        int d[9];
        d[0] = (e0 == 0) ? -1 : __ldg(dst + e0 - 1);
        d[1] = dA.x; d[2] = dA.y; d[3] = dA.z; d[4] = dA.w;
        d[5] = dB.x; d[6] = dB.y; d[7] = dB.z; d[8] = dB.w;
        #pragma unroll
        for (int j = 0; j < 8; j++) {
            // boundary e = e0 + j: fill row_start[n] = e for n in (d[j], d[j+1]]
            for (int n = d[j] + 1; n <= d[j + 1]; n++)
                g_row_start[n] = e0 + j;
        }
    } else {
        // tail (includes boundary e == E)
        for (int e = e0; e <= E; e++) {
            int dprev = (e == 0) ? -1 : __ldg(dst + e - 1);
            int dcur  = (e == E) ? N - 1 : __ldg(dst + e);
            for (int n = dprev + 1; n <= dcur; n++)
                g_row_start[n] = e;
            if (e == E) {
                // ensure row_start[N] set
                g_row_start[N] = E;
            }
        }
    }
    if (e0 == 0) {
        // guard: row_start[N] written by tail thread; also handle E%8==0 case
        // (tail loop above covers e==E when e0+8>E; if E%8==0 the owner is
        //  thread gid=E/8 whose e0==E, handled by the tail branch.)
    }
}

// ===========================================================================
// Kernel 1: GEMM  support[M,128] = X[M,256] @ W[256,128], fp16 MMA.
// Block 128x128, 8 warps (2x4), warp tile 64x32, BK=32 fp32; 2 CTAs/SM.
// Whole W (fp16, preconverted) resident in SMEM; A tiles double-buffered.
// ===========================================================================
#define BKC 32
#define A_STRIDE 40
#define B_STRIDE 136
#define A_BUF_BYTES (128 * A_STRIDE * 2)
#define SM_A   0
#define SM_B   (2 * A_BUF_BYTES)
#define SM_TOTAL (SM_B + IN_F * B_STRIDE * 2)      // 90112

__global__ void __launch_bounds__(256, 2)
gemm_mma_kernel(const float* __restrict__ X, int M)
{
    extern __shared__ __align__(16) char smem[];
    const uint32_t sb = smem_u32(smem);

    const int tid    = threadIdx.x;
    const int lane   = tid & 31;
    const int wid    = tid >> 5;
    const int warp_m = (wid & 1) * 64;
    const int warp_n = (wid >> 1) * 32;
    const int row0   = blockIdx.x << 7;

    {
        const uint4* wp = reinterpret_cast<const uint4*>(g_wh);
        #pragma unroll
        for (int i = 0; i < 16; i++) {
            int e = tid + i * 256;
            int k = e >> 4, u = e & 15;
            uint4 h = wp[(size_t)k * 16 + u];
            uint32_t off = (uint32_t)(k * (B_STRIDE * 2) + u * 16);
            asm volatile("st.shared.v4.b32 [%0], {%1,%2,%3,%4};"
                         :: "r"(sb + SM_B + off), "r"(h.x), "r"(h.y), "r"(h.z), "r"(h.w) : "memory");
        }
    }

    float acc[4][4][4];
    #pragma unroll
    for (int i = 0; i < 4; i++)
        #pragma unroll
        for (int j = 0; j < 4; j++)
            #pragma unroll
            for (int q = 0; q < 4; q++) acc[i][j][q] = 0.f;

    const int a_r  = tid >> 3;
    const int a_kq = tid & 7;

    float4 xa[4];
    #pragma unroll
    for (int i = 0; i < 4; i++) {
        int gr = row0 + a_r + i * 32;
        xa[i] = (gr < M) ? *reinterpret_cast<const float4*>(X + (size_t)gr * IN_F + a_kq * 4)
                         : make_float4(0.f, 0.f, 0.f, 0.f);
    }
    #pragma unroll
    for (int i = 0; i < 4; i++) {
        int r = a_r + i * 32;
        uint32_t h0 = packh2(xa[i].x, xa[i].y), h1 = packh2(xa[i].z, xa[i].w);
        uint32_t off = (uint32_t)(r * (A_STRIDE * 2) + a_kq * 8);
        asm volatile("st.shared.v2.b32 [%0], {%1,%2};" :: "r"(sb + SM_A + off), "r"(h0), "r"(h1) : "memory");
    }
    __syncthreads();

    for (int c = 0; c < IN_F / BKC; c++) {
        const uint32_t abuf = sb + SM_A + (uint32_t)(c & 1) * A_BUF_BYTES;
        const bool more = (c + 1 < IN_F / BKC);

        if (more) {
            int k0n = (c + 1) * BKC;
            #pragma unroll
            for (int i = 0; i < 4; i++) {
                int gr = row0 + a_r + i * 32;
                xa[i] = (gr < M) ? *reinterpret_cast<const float4*>(X + (size_t)gr * IN_F + k0n + a_kq * 4)
                                 : make_float4(0.f, 0.f, 0.f, 0.f);
            }
        }

        #pragma unroll
        for (int ks = 0; ks < 2; ks++) {
            uint32_t ah[4][4], bh[2][4];
            const uint32_t a_col = (uint32_t)((ks * 16 + (lane >> 4) * 8) * 2);
            #pragma unroll
            for (int mi = 0; mi < 4; mi++) {
                uint32_t ar = (uint32_t)((warp_m + mi * 16 + (lane & 15)) * (A_STRIDE * 2)) + a_col;
                ldsm_x4(ah[mi], abuf + ar);
            }
            const uint32_t b_row =
                (uint32_t)((c * 32 + ks * 16 + (lane & 7) + ((lane >> 3) & 1) * 8) * (B_STRIDE * 2));
            #pragma unroll
            for (int nj = 0; nj < 2; nj++) {
                uint32_t br = b_row + (uint32_t)((warp_n + nj * 16 + (lane >> 4) * 8) * 2);
                ldsm_x4_t(bh[nj], sb + SM_B + br);
            }
            #pragma unroll
            for (int mi = 0; mi < 4; mi++) {
                #pragma unroll
                for (int nj = 0; nj < 4; nj++) {
                    uint32_t bf[2] = { bh[nj >> 1][(nj & 1) * 2], bh[nj >> 1][(nj & 1) * 2 + 1] };
                    mma_fp16(acc[mi][nj], ah[mi], bf);
                }
            }
        }

        if (more) {
            const uint32_t nbuf = sb + SM_A + (uint32_t)((c + 1) & 1) * A_BUF_BYTES;
            #pragma unroll
            for (int i = 0; i < 4; i++) {
                int r = a_r + i * 32;
                uint32_t h0 = packh2(xa[i].x, xa[i].y), h1 = packh2(xa[i].z, xa[i].w);
                uint32_t off = (uint32_t)(r * (A_STRIDE * 2) + a_kq * 8);
                asm volatile("st.shared.v2.b32 [%0], {%1,%2};" :: "r"(nbuf + off), "r"(h0), "r"(h1) : "memory");
            }
        }
        __syncthreads();
    }

    #pragma unroll
    for (int mi = 0; mi < 4; mi++) {
        int r_lo = row0 + warp_m + mi * 16 + (lane >> 2);
        int r_hi = r_lo + 8;
        #pragma unroll
        for (int nj = 0; nj < 4; nj++) {
            int col = warp_n + nj * 8 + (lane & 3) * 2;
            if (r_lo < M)
                g_support_h[(size_t)r_lo * (OUT_F / 2) + (col >> 1)] =
                    __floats2half2_rn(acc[mi][nj][0], acc[mi][nj][1]);
            if (r_hi < M)
                g_support_h[(size_t)r_hi * (OUT_F / 2) + (col >> 1)] =
                    __floats2half2_rn(acc[mi][nj][2], acc[mi][nj][3]);
        }
    }
}

// ===========================================================================
// Kernel 2: aggregation + bias + tanh.
// One warp per node, precomputed bounds, 8-edge unroll.
// ===========================================================================
#define FMA4(vv, rr)                                                         \
    do {                                                                     \
        float2 _f0 = __half22float2(*reinterpret_cast<__half2*>(&(rr).x));   \
        float2 _f1 = __half22float2(*reinterpret_cast<__half2*>(&(rr).y));   \
        a0 += (vv) * _f0.x; a1 += (vv) * _f0.y;                              \
        a2 += (vv) * _f1.x; a3 += (vv) * _f1.y;                              \
    } while (0)

__global__ __launch_bounds__(128)
void aggregate_kernel(const int*   __restrict__ src,
                      const float* __restrict__ val,
                      const float* __restrict__ bias,
                      float*       __restrict__ out,
                      int N)
{
    const int n = blockIdx.x * 4 + (threadIdx.x >> 5);
    if (n >= N) return;
    const int lane = threadIdx.x & 31;

    const uint2* __restrict__ sup = reinterpret_cast<const uint2*>(g_support_h);

    int i       = g_row_start[n];
    const int e = g_row_start[n + 1];

    float a0 = 0.f, a1 = 0.f, a2 = 0.f, a3 = 0.f;

    for (; i < e && (i & 3); i++) {
        float v = val[i];
        uint2 r = __ldg(sup + ((uint32_t)src[i] << 5) + lane);
        FMA4(v, r);
    }
    for (; i + 8 <= e; i += 8) {
        int4   sA = *reinterpret_cast<const int4*>(src + i);
        int4   sB = *reinterpret_cast<const int4*>(src + i + 4);
        float4 vA = *reinterpret_cast<const float4*>(val + i);
        float4 vB = *reinterpret_cast<const float4*>(val + i + 4);
        uint2 r0 = __ldg(sup + ((uint32_t)sA.x << 5) + lane);
        uint2 r1 = __ldg(sup + ((uint32_t)sA.y << 5) + lane);
        uint2 r2 = __ldg(sup + ((uint32_t)sA.z << 5) + lane);
        uint2 r3 = __ldg(sup + ((uint32_t)sA.w << 5) + lane);
        uint2 r4 = __ldg(sup + ((uint32_t)sB.x << 5) + lane);
        uint2 r5 = __ldg(sup + ((uint32_t)sB.y << 5) + lane);
        uint2 r6 = __ldg(sup + ((uint32_t)sB.z << 5) + lane);
        uint2 r7 = __ldg(sup + ((uint32_t)sB.w << 5) + lane);
        FMA4(vA.x, r0); FMA4(vA.y, r1); FMA4(vA.z, r2); FMA4(vA.w, r3);
        FMA4(vB.x, r4); FMA4(vB.y, r5); FMA4(vB.z, r6); FMA4(vB.w, r7);
    }
    for (; i + 4 <= e; i += 4) {
        int4   sA = *reinterpret_cast<const int4*>(src + i);
        float4 vA = *reinterpret_cast<const float4*>(val + i);
        uint2 r0 = __ldg(sup + ((uint32_t)sA.x << 5) + lane);
        uint2 r1 = __ldg(sup + ((uint32_t)sA.y << 5) + lane);
        uint2 r2 = __ldg(sup + ((uint32_t)sA.z << 5) + lane);
        uint2 r3 = __ldg(sup + ((uint32_t)sA.w << 5) + lane);
        FMA4(vA.x, r0); FMA4(vA.y, r1); FMA4(vA.z, r2); FMA4(vA.w, r3);
    }
    for (; i < e; i++) {
        float v = val[i];
        uint2 r = __ldg(sup + ((uint32_t)src[i] << 5) + lane);
        FMA4(v, r);
    }

    float4 b = *reinterpret_cast<const float4*>(bias + lane * 4);
    *reinterpret_cast<float4*>(out + (size_t)n * OUT_F + lane * 4) =
        make_float4(tanhf(a0 + b.x), tanhf(a1 + b.y),
                    tanhf(a2 + b.z), tanhf(a3 + b.w));
}

// ===========================================================================
// Launch
// ===========================================================================
extern "C" void kernel_launch(void* const* d_in, const int* in_sizes, int n_in,
                              void* d_out, int out_size)
{
    const float* x        = (const float*)d_in[0];
    const float* weight   = (const float*)d_in[1];
    const float* bias     = (const float*)d_in[2];
    const int*   edge_src = (const int*)  d_in[3];
    const int*   edge_dst = (const int*)  d_in[4];
    const float* edge_val = (const float*)d_in[5];
    float*       out      = (float*)d_out;

    const int M = in_sizes[0] / IN_F;   // 100000
    const int E = in_sizes[3];          // 1600000

    static bool attr_done = false;
    if (!attr_done) {
        cudaFuncSetAttribute(gemm_mma_kernel,
                             cudaFuncAttributeMaxDynamicSharedMemorySize, SM_TOTAL);
        attr_done = true;
    }

    // 0) prep: W convert + CSR boundaries (vectorized, 8 boundaries/thread)
    {
        int nthreads = E / 8 + 2;            // covers all boundary owners + tail
        if (nthreads < IN_F * OUT_F) nthreads = IN_F * OUT_F;
        prep_kernel<<<(nthreads + 255) / 256, 256>>>(weight, edge_dst, E, M);
    }
    // 1) support = X @ W on tensor cores (fp16)
    gemm_mma_kernel<<<(M + 127) / 128, 256, SM_TOTAL>>>(x, M);
    // 2) gather + segment-sum + bias + tanh (one warp per node)
    aggregate_kernel<<<(M + 3) / 4, 128>>>(edge_src, edge_val, bias, out, M);
}